// round 12
// baseline (speedup 1.0000x reference)
#include <cuda_runtime.h>
#include <cuda_bf16.h>
#include <cuda_fp16.h>
#include <math.h>

// ---------------- problem constants ----------------
#define N_NODES 100000
#define N_EDGES 3200000
#define IN_F    500
#define HID     64
#define OUT_F   64
#define ALPHA   0.1f
#define K_ITERS 10

#define NSCAN_BLOCKS ((N_NODES + 1023) / 1024)   // 98
#define KK 8                                      // gemm k-tile
#define SCALE_S 0.0625                            // 1/16 per-iteration z scaling
#define WQ_SCALE 32767.0f
#define WQ_INV   (1.0f / 32767.0f)

typedef unsigned long long u64;

// ---------------- static device scratch ----------------
__device__ float    g_h1[N_NODES * HID];          // relu(x@W1+b1)
__device__ float    g_h [N_NODES * OUT_F];        // fp32 h (final iter)
__device__ __half   g_hh[N_NODES * OUT_F];        // fp16 h (= y_0, alpha term)
__device__ __half   g_ya[N_NODES * OUT_F];        // fp16 iterate ping
__device__ __half   g_yb[N_NODES * OUT_F];        // fp16 iterate pong
__device__ int      g_deg[N_NODES];               // ALWAYS zero at launch entry
__device__ int      g_off[N_NODES + 1];
__device__ int      g_pos[N_NODES];
__device__ unsigned g_epk[N_EDGES];               // packed edge: w15 | src17
__device__ int      g_bsum[NSCAN_BLOCKS];

// ---------------- f32x2 helpers ----------------
__device__ __forceinline__ u64 pack2(float x, float y) {
    u64 r; asm("mov.b64 %0, {%1, %2};" : "=l"(r) : "f"(x), "f"(y)); return r;
}
__device__ __forceinline__ void unpack2(float& x, float& y, u64 v) {
    asm("mov.b64 {%0, %1}, %2;" : "=f"(x), "=f"(y) : "l"(v));
}
#define FMA2(acc, a, b) asm("fma.rn.f32x2 %0, %1, %2, %0;" : "+l"(acc) : "l"(a), "l"(b))

// ---------------- CSR construction (4 kernels) ----------------
__global__ void hist_kernel(const int* __restrict__ dst) {
    int i = blockIdx.x * blockDim.x + threadIdx.x;
    if (i * 4 + 3 < N_EDGES) {
        int4 d = ((const int4*)dst)[i];
        atomicAdd(&g_deg[d.x], 1);
        atomicAdd(&g_deg[d.y], 1);
        atomicAdd(&g_deg[d.z], 1);
        atomicAdd(&g_deg[d.w], 1);
    } else {
        for (int e = i * 4; e < N_EDGES; e++) atomicAdd(&g_deg[dst[e]], 1);
    }
}

__global__ void scan_local_kernel() {
    __shared__ int s[1024];
    int tid = threadIdx.x;
    int i = blockIdx.x * 1024 + tid;
    int v = (i < N_NODES) ? g_deg[i] : 0;
    s[tid] = v;
    __syncthreads();
    #pragma unroll
    for (int d = 1; d < 1024; d <<= 1) {
        int t = (tid >= d) ? s[tid - d] : 0;
        __syncthreads();
        s[tid] += t;
        __syncthreads();
    }
    if (i < N_NODES) {
        g_off[i] = s[tid] - v;     // exclusive local
        g_deg[i] = 0;              // restore zero invariant for next launch
    }
    if (tid == 1023) g_bsum[blockIdx.x] = s[1023];
}

__global__ void scan_add_kernel() {
    __shared__ int red[32];
    int tid  = threadIdx.x;
    int lane = tid & 31;
    int wid  = tid >> 5;
    int pre = 0;
    for (int t = tid; t < blockIdx.x; t += 1024) pre += g_bsum[t];
    #pragma unroll
    for (int d = 16; d; d >>= 1) pre += __shfl_down_sync(0xffffffffu, pre, d);
    if (lane == 0) red[wid] = pre;
    __syncthreads();
    if (wid == 0) {
        int v = red[lane];
        #pragma unroll
        for (int d = 16; d; d >>= 1) v += __shfl_down_sync(0xffffffffu, v, d);
        if (lane == 0) red[0] = v;
    }
    __syncthreads();
    int base = red[0];

    int i = blockIdx.x * 1024 + tid;
    if (i < N_NODES) {
        int o = g_off[i] + base;
        g_off[i] = o;
        g_pos[i] = o;
    }
    if (blockIdx.x == 0 && tid == 0) g_off[N_NODES] = N_EDGES;
}

__global__ void scatter_kernel(const int* __restrict__ src,
                               const int* __restrict__ dst,
                               const float* __restrict__ w) {
    int e = blockIdx.x * blockDim.x + threadIdx.x;
    if (e < N_EDGES) {
        int d = dst[e];
        int p = atomicAdd(&g_pos[d], 1);
        unsigned q = (unsigned)__float2int_rn(w[e] * WQ_SCALE);
        g_epk[p] = (q << 17) | (unsigned)src[e];
    }
}

// ---------------- GEMM: C[n,64] = act(A[n,K] @ W[K,64] + b) ----------------
// Double-buffered staging: prefetch tile t+1 into registers while computing
// tile t from smem; STS into the opposite buffer; one sync per tile.
template <bool RELU, bool WRITE_HALF>
__global__ __launch_bounds__(256)
void gemm128_kernel(const float* __restrict__ A, const float* __restrict__ W,
                    const float* __restrict__ bias, float* __restrict__ C,
                    __half* __restrict__ Yh, int nrows, int K) {
    __shared__ __align__(16) u64 xs[2][128 * KK];
    __shared__ __align__(16) u64 ws[2][KK * 32];

    const int tid  = threadIdx.x;
    const int w    = tid >> 5;
    const int lane = tid & 31;
    const int rh   = lane >> 4;
    const int cg   = lane & 15;
    const int rbase = w * 16 + rh * 8;
    const int row0  = blockIdx.x * 128;

    const int xr[4] = { (tid) >> 3, (tid + 256) >> 3, (tid + 512) >> 3, (tid + 768) >> 3 };
    const int xk = tid & 7;
    const int wkk = tid >> 5;
    const int wp  = tid & 31;

    u64 acc[8][2];
    #pragma unroll
    for (int r = 0; r < 8; r++) { acc[r][0] = 0ull; acc[r][1] = 0ull; }

    const int ktiles = (K + KK - 1) / KK;

    float xv[4];
    float wv0, wv1;

    {
        #pragma unroll
        for (int j = 0; j < 4; j++) {
            int gr = row0 + xr[j];
            xv[j] = (gr < nrows && xk < K) ? __ldg(&A[(long)gr * K + xk]) : 0.f;
        }
        wv0 = (wkk < K) ? W[wkk * 64 + 2 * wp]     : 0.f;
        wv1 = (wkk < K) ? W[wkk * 64 + 2 * wp + 1] : 0.f;
    }
    #pragma unroll
    for (int j = 0; j < 4; j++) xs[0][xr[j] * KK + xk] = pack2(xv[j], xv[j]);
    ws[0][wkk * 32 + wp] = pack2(wv0, wv1);
    __syncthreads();

    for (int t = 0; t < ktiles; t++) {
        const int buf = t & 1;
        if (t + 1 < ktiles) {
            const int ko = (t + 1) * KK;
            #pragma unroll
            for (int j = 0; j < 4; j++) {
                int gr = row0 + xr[j];
                int gk = ko + xk;
                xv[j] = (gr < nrows && gk < K) ? __ldg(&A[(long)gr * K + gk]) : 0.f;
            }
            int gk = ko + wkk;
            wv0 = (gk < K) ? W[gk * 64 + 2 * wp]     : 0.f;
            wv1 = (gk < K) ? W[gk * 64 + 2 * wp + 1] : 0.f;
        }

        u64 wr[KK][2];
        #pragma unroll
        for (int kk = 0; kk < KK; kk++) {
            ulonglong2 wv = *(const ulonglong2*)&ws[buf][kk * 32 + 2 * cg];
            wr[kk][0] = wv.x; wr[kk][1] = wv.y;
        }
        #pragma unroll
        for (int kk2 = 0; kk2 < KK / 2; kk2++) {
            #pragma unroll
            for (int r = 0; r < 8; r++) {
                ulonglong2 xq = *(const ulonglong2*)&xs[buf][(rbase + r) * KK + 2 * kk2];
                FMA2(acc[r][0], xq.x, wr[2 * kk2][0]);
                FMA2(acc[r][1], xq.x, wr[2 * kk2][1]);
                FMA2(acc[r][0], xq.y, wr[2 * kk2 + 1][0]);
                FMA2(acc[r][1], xq.y, wr[2 * kk2 + 1][1]);
            }
        }

        if (t + 1 < ktiles) {
            #pragma unroll
            for (int j = 0; j < 4; j++) xs[buf ^ 1][xr[j] * KK + xk] = pack2(xv[j], xv[j]);
            ws[buf ^ 1][wkk * 32 + wp] = pack2(wv0, wv1);
            __syncthreads();
        }
    }

    float4 b4 = *(const float4*)&bias[4 * cg];
    #pragma unroll
    for (int r = 0; r < 8; r++) {
        int row = row0 + rbase + r;
        if (row < nrows) {
            float c0, c1, c2, c3;
            unpack2(c0, c1, acc[r][0]);
            unpack2(c2, c3, acc[r][1]);
            c0 += b4.x; c1 += b4.y; c2 += b4.z; c3 += b4.w;
            if (RELU) {
                c0 = fmaxf(c0, 0.f); c1 = fmaxf(c1, 0.f);
                c2 = fmaxf(c2, 0.f); c3 = fmaxf(c3, 0.f);
            }
            *(float4*)&C[(long)row * 64 + 4 * cg] = make_float4(c0, c1, c2, c3);
            if (WRITE_HALF) {
                long yi = (long)row * 64 + 4 * cg;
                __half2 p0 = __floats2half2_rn(c0, c1);
                __half2 p1 = __floats2half2_rn(c2, c3);
                uint2 pv; pv.x = *(unsigned*)&p0; pv.y = *(unsigned*)&p1;
                *(uint2*)&Yh[yi] = pv;
            }
        }
    }
}

// ---------------- APPNP propagation (CONVERGENT quarter-warp) ----------------
// Warp per node; 4 quarters (8 lanes) each process a different edge:
// 1 shfl + 1 LDG.128 advances FOUR edges. The warp NEVER diverges:
//  - full batches: every quarter runs exactly 8 unrolled steps (width-8,
//    full-mask shfl — legal, warp converged);
//  - tail: balanced split jcnt=ceil(cnt/4); ALL quarters run jcnt steps with
//    per-lane source q*jcnt+j (width-32, full-mask); out-of-range sources
//    hold pe=0 => w=0, contributes nothing (<=3 wasted steps per node).
#define QBODY(PJ) {                                                           \
    float wj = (float)((PJ) >> 17) * WQ_INV;                                  \
    uint4 v = __ldg((const uint4*)(yin + ((long)((PJ) & 0x1FFFFu) << 6)) + ql); \
    float2 f0 = __half22float2(*(__half2*)&v.x);                              \
    float2 f1 = __half22float2(*(__half2*)&v.y);                              \
    float2 f2 = __half22float2(*(__half2*)&v.z);                              \
    float2 f3 = __half22float2(*(__half2*)&v.w);                              \
    acc0 = fmaf(wj, f0.x, acc0); acc1 = fmaf(wj, f0.y, acc1);                 \
    acc2 = fmaf(wj, f1.x, acc2); acc3 = fmaf(wj, f1.y, acc3);                 \
    acc4 = fmaf(wj, f2.x, acc4); acc5 = fmaf(wj, f2.y, acc5);                 \
    acc6 = fmaf(wj, f3.x, acc6); acc7 = fmaf(wj, f3.y, acc7); }

template <bool FINAL>
__global__ __launch_bounds__(256)
void prop_kernel(const __half* __restrict__ yin,
                 const uint4* __restrict__ hh, const float4* __restrict__ h4,
                 uint4* __restrict__ yout, float4* __restrict__ fout,
                 float c1, float c2) {
    int gtid = blockIdx.x * blockDim.x + threadIdx.x;
    int node = gtid >> 5;
    int lane = threadIdx.x & 31;
    if (node >= N_NODES) return;
    const int ql = lane & 7;                      // lane in quarter
    const int q  = lane >> 3;                     // quarter id

    int beg = g_off[node];
    int end = g_off[node + 1];

    float acc0 = 0.f, acc1 = 0.f, acc2 = 0.f, acc3 = 0.f;
    float acc4 = 0.f, acc5 = 0.f, acc6 = 0.f, acc7 = 0.f;

    int e = beg;
    // full 32-edge batches: uniform 8 steps per quarter, warp converged
    for (; e + 32 <= end; e += 32) {
        unsigned pe = __ldg(&g_epk[e + lane]);
        #pragma unroll
        for (int j = 0; j < 8; j++) {
            unsigned pj = __shfl_sync(0xffffffffu, pe, j, 8);  // quarter-local j
            QBODY(pj)
        }
    }
    // tail: balanced, ALL quarters run jcnt steps (no divergence)
    if (e < end) {
        int idx = e + lane;
        unsigned pe = (idx < end) ? __ldg(&g_epk[idx]) : 0u;
        int cnt  = end - e;                       // 1..31
        int jcnt = (cnt + 3) >> 2;                // ceil(cnt/4) <= 8
        int src0 = q * jcnt;                      // this quarter's source base
        for (int j = 0; j < jcnt; j++) {
            unsigned pj = __shfl_sync(0xffffffffu, pe, src0 + j, 32);
            QBODY(pj)                             // overflow lanes: pe=0 => w=0
        }
    }

    #define XRED(A) A += __shfl_xor_sync(0xffffffffu, A, 8);  \
                    A += __shfl_xor_sync(0xffffffffu, A, 16);
    XRED(acc0) XRED(acc1) XRED(acc2) XRED(acc3)
    XRED(acc4) XRED(acc5) XRED(acc6) XRED(acc7)
    #undef XRED

    if (lane < 8) {
        long oi = (long)node * 8 + ql;            // 8-half (uint4) granularity
        if (FINAL) {
            float4 ha = h4[oi * 2];
            float4 hb = h4[oi * 2 + 1];
            fout[oi * 2]     = make_float4(fmaf(c1, acc0, c2 * ha.x),
                                           fmaf(c1, acc1, c2 * ha.y),
                                           fmaf(c1, acc2, c2 * ha.z),
                                           fmaf(c1, acc3, c2 * ha.w));
            fout[oi * 2 + 1] = make_float4(fmaf(c1, acc4, c2 * hb.x),
                                           fmaf(c1, acc5, c2 * hb.y),
                                           fmaf(c1, acc6, c2 * hb.z),
                                           fmaf(c1, acc7, c2 * hb.w));
        } else {
            uint4 hv = hh[oi];
            float2 g0 = __half22float2(*(__half2*)&hv.x);
            float2 g1 = __half22float2(*(__half2*)&hv.y);
            float2 g2 = __half22float2(*(__half2*)&hv.z);
            float2 g3 = __half22float2(*(__half2*)&hv.w);
            __half2 p0 = __floats2half2_rn(fmaf(c1, acc0, c2 * g0.x),
                                           fmaf(c1, acc1, c2 * g0.y));
            __half2 p1 = __floats2half2_rn(fmaf(c1, acc2, c2 * g1.x),
                                           fmaf(c1, acc3, c2 * g1.y));
            __half2 p2 = __floats2half2_rn(fmaf(c1, acc4, c2 * g2.x),
                                           fmaf(c1, acc5, c2 * g2.y));
            __half2 p3 = __floats2half2_rn(fmaf(c1, acc6, c2 * g3.x),
                                           fmaf(c1, acc7, c2 * g3.y));
            uint4 pv;
            pv.x = *(unsigned*)&p0; pv.y = *(unsigned*)&p1;
            pv.z = *(unsigned*)&p2; pv.w = *(unsigned*)&p3;
            yout[oi] = pv;
        }
    }
}

// ---------------- launch ----------------
extern "C" void kernel_launch(void* const* d_in, const int* in_sizes, int n_in,
                              void* d_out, int out_size) {
    const float* x    = (const float*)d_in[0];
    const int*   esrc = (const int*)d_in[1];
    const int*   edst = (const int*)d_in[2];
    const float* ew   = (const float*)d_in[3];
    const float* W1   = (const float*)d_in[4];
    const float* b1   = (const float*)d_in[5];
    const float* W2   = (const float*)d_in[6];
    const float* b2   = (const float*)d_in[7];
    float* out = (float*)d_out;

    static cudaStream_t s_side = nullptr;
    static cudaEvent_t  s_evFork = nullptr, s_evJoin = nullptr;
    if (!s_side) {
        cudaStreamCreateWithFlags(&s_side, cudaStreamNonBlocking);
        cudaEventCreateWithFlags(&s_evFork, cudaEventDisableTiming);
        cudaEventCreateWithFlags(&s_evJoin, cudaEventDisableTiming);
    }

    float  *h1_p, *h_p;
    __half *hh_p, *ya_p, *yb_p;
    cudaGetSymbolAddress((void**)&h1_p, g_h1);
    cudaGetSymbolAddress((void**)&h_p,  g_h);
    cudaGetSymbolAddress((void**)&hh_p, g_hh);
    cudaGetSymbolAddress((void**)&ya_p, g_ya);
    cudaGetSymbolAddress((void**)&yb_p, g_yb);

    // --- fork: CSR build on side stream, concurrent with MLP GEMMs ---
    cudaEventRecord(s_evFork, 0);
    cudaStreamWaitEvent(s_side, s_evFork, 0);
    hist_kernel<<<(N_EDGES / 4 + 255) / 256, 256, 0, s_side>>>(edst);
    scan_local_kernel<<<NSCAN_BLOCKS, 1024, 0, s_side>>>();
    scan_add_kernel<<<NSCAN_BLOCKS, 1024, 0, s_side>>>();
    scatter_kernel<<<(N_EDGES + 255) / 256, 256, 0, s_side>>>(esrc, edst, ew);
    cudaEventRecord(s_evJoin, s_side);

    // --- MLP encoder on main stream (GEMM2 also emits y_0 = fp16(h)) ---
    int gblocks = (N_NODES + 127) / 128;
    gemm128_kernel<true,  false><<<gblocks, 256>>>(x,    W1, b1, h1_p, nullptr, N_NODES, IN_F);
    gemm128_kernel<false, true ><<<gblocks, 256>>>(h1_p, W2, b2, h_p,  hh_p,    N_NODES, HID);

    // --- join, then K propagation steps ---
    cudaStreamWaitEvent(0, s_evJoin, 0);

    int pblocks = (N_NODES * 32 + 255) / 256;
    const __half* yin = hh_p;                 // y_0 = fp16(h)
    __half* ybufs[2] = { ya_p, yb_p };
    for (int k = 0; k < K_ITERS; k++) {
        if (k < K_ITERS - 1) {
            float c1 = (float)(0.9 * SCALE_S);
            float c2 = (float)(0.1 * pow(SCALE_S, (double)(k + 1)));
            __half* yo = ybufs[k & 1];
            prop_kernel<false><<<pblocks, 256>>>(yin, (const uint4*)hh_p, nullptr,
                                                 (uint4*)yo, nullptr, c1, c2);
            yin = yo;
        } else {
            float c1 = (float)(0.9 * pow(1.0 / SCALE_S, (double)(K_ITERS - 1)));
            float c2 = 0.1f;
            prop_kernel<true><<<pblocks, 256>>>(yin, nullptr, (const float4*)h_p,
                                                nullptr, (float4*)out, c1, c2);
        }
    }
}

// round 13
// speedup vs baseline: 1.1003x; 1.1003x over previous
#include <cuda_runtime.h>
#include <cuda_bf16.h>
#include <cuda_fp16.h>
#include <math.h>

// ---------------- problem constants ----------------
#define N_NODES 100000
#define N_EDGES 3200000
#define IN_F    500
#define HID     64
#define OUT_F   64
#define ALPHA   0.1f
#define K_ITERS 10

#define NSCAN_BLOCKS ((N_NODES + 1023) / 1024)   // 98
#define KK 8                                      // fp32 gemm k-tile (GEMM2)
#define SCALE_S 0.0625                            // 1/16 per-iteration z scaling
#define WQ_SCALE 32767.0f
#define WQ_INV   (1.0f / 32767.0f)

typedef unsigned long long u64;

// ---------------- static device scratch ----------------
__device__ float    g_h1[N_NODES * HID];          // relu(x@W1+b1)
__device__ float    g_h [N_NODES * OUT_F];        // fp32 h (final iter)
__device__ __half   g_hh[N_NODES * OUT_F];        // fp16 h (= y_0, alpha term)
__device__ __half   g_ya[N_NODES * OUT_F];        // fp16 iterate ping
__device__ __half   g_yb[N_NODES * OUT_F];        // fp16 iterate pong
__device__ int      g_deg[N_NODES];               // ALWAYS zero at launch entry
__device__ int      g_off[N_NODES + 1];
__device__ int      g_pos[N_NODES];
__device__ unsigned g_epk[N_EDGES];               // packed edge: w15 | src17
__device__ int      g_bsum[NSCAN_BLOCKS];

// ---------------- f32x2 helpers ----------------
__device__ __forceinline__ u64 pack2(float x, float y) {
    u64 r; asm("mov.b64 %0, {%1, %2};" : "=l"(r) : "f"(x), "f"(y)); return r;
}
__device__ __forceinline__ void unpack2(float& x, float& y, u64 v) {
    asm("mov.b64 {%0, %1}, %2;" : "=f"(x), "=f"(y) : "l"(v));
}
#define FMA2(acc, a, b) asm("fma.rn.f32x2 %0, %1, %2, %0;" : "+l"(acc) : "l"(a), "l"(b))

// ---------------- CSR construction (4 kernels) ----------------
__global__ void hist_kernel(const int* __restrict__ dst) {
    int i = blockIdx.x * blockDim.x + threadIdx.x;
    if (i * 4 + 3 < N_EDGES) {
        int4 d = ((const int4*)dst)[i];
        atomicAdd(&g_deg[d.x], 1);
        atomicAdd(&g_deg[d.y], 1);
        atomicAdd(&g_deg[d.z], 1);
        atomicAdd(&g_deg[d.w], 1);
    } else {
        for (int e = i * 4; e < N_EDGES; e++) atomicAdd(&g_deg[dst[e]], 1);
    }
}

__global__ void scan_local_kernel() {
    __shared__ int s[1024];
    int tid = threadIdx.x;
    int i = blockIdx.x * 1024 + tid;
    int v = (i < N_NODES) ? g_deg[i] : 0;
    s[tid] = v;
    __syncthreads();
    #pragma unroll
    for (int d = 1; d < 1024; d <<= 1) {
        int t = (tid >= d) ? s[tid - d] : 0;
        __syncthreads();
        s[tid] += t;
        __syncthreads();
    }
    if (i < N_NODES) {
        g_off[i] = s[tid] - v;     // exclusive local
        g_deg[i] = 0;              // restore zero invariant for next launch
    }
    if (tid == 1023) g_bsum[blockIdx.x] = s[1023];
}

__global__ void scan_add_kernel() {
    __shared__ int red[32];
    int tid  = threadIdx.x;
    int lane = tid & 31;
    int wid  = tid >> 5;
    int pre = 0;
    for (int t = tid; t < blockIdx.x; t += 1024) pre += g_bsum[t];
    #pragma unroll
    for (int d = 16; d; d >>= 1) pre += __shfl_down_sync(0xffffffffu, pre, d);
    if (lane == 0) red[wid] = pre;
    __syncthreads();
    if (wid == 0) {
        int v = red[lane];
        #pragma unroll
        for (int d = 16; d; d >>= 1) v += __shfl_down_sync(0xffffffffu, v, d);
        if (lane == 0) red[0] = v;
    }
    __syncthreads();
    int base = red[0];

    int i = blockIdx.x * 1024 + tid;
    if (i < N_NODES) {
        int o = g_off[i] + base;
        g_off[i] = o;
        g_pos[i] = o;
    }
    if (blockIdx.x == 0 && tid == 0) g_off[N_NODES] = N_EDGES;
}

__global__ void scatter_kernel(const int* __restrict__ src,
                               const int* __restrict__ dst,
                               const float* __restrict__ w) {
    int e = blockIdx.x * blockDim.x + threadIdx.x;
    if (e < N_EDGES) {
        int d = dst[e];
        int p = atomicAdd(&g_pos[d], 1);
        unsigned q = (unsigned)__float2int_rn(w[e] * WQ_SCALE);
        g_epk[p] = (q << 17) | (unsigned)src[e];
    }
}

// ---------------- GEMM1 (tensor cores): C = relu(A[n,500]@W[500,64] + b) ----
// bf16 hi/lo split, 3 MMA passes (hi*hi + hi*lo + lo*hi), fp32 accumulate.
// Block = 128 rows x 64 cols, 8 warps in 4(m) x 2(n) grid.
// Warp tile = 32 rows x 32 cols = 2 m-tiles x 4 n-tiles of m16n8k16.
// smem stride 40 bf16/row => A/B fragment LDS.32 loads are bank-conflict-free.
#define XS_STRIDE 40
#define MMA_BF16(d, a, b0_, b1_)                                              \
    asm volatile("mma.sync.aligned.m16n8k16.row.col.f32.bf16.bf16.f32 "       \
                 "{%0,%1,%2,%3}, {%4,%5,%6,%7}, {%8,%9}, {%0,%1,%2,%3};"      \
                 : "+f"(d[0]), "+f"(d[1]), "+f"(d[2]), "+f"(d[3])             \
                 : "r"(a[0]), "r"(a[1]), "r"(a[2]), "r"(a[3]),                \
                   "r"(b0_), "r"(b1_))

__global__ __launch_bounds__(256)
void gemm1_tc_kernel(const float* __restrict__ A, const float* __restrict__ W,
                     const float* __restrict__ bias, float* __restrict__ C,
                     int nrows, int K) {
    __shared__ unsigned short xs_hi[128 * XS_STRIDE];
    __shared__ unsigned short xs_lo[128 * XS_STRIDE];
    __shared__ unsigned short wt_hi[64 * XS_STRIDE];   // W transposed [n][k]
    __shared__ unsigned short wt_lo[64 * XS_STRIDE];

    const int tid  = threadIdx.x;
    const int wid  = tid >> 5;
    const int lane = tid & 31;
    const int g    = lane >> 2;          // fragment group row
    const int tg2  = (lane & 3) * 2;     // fragment pair column
    const int warp_m = wid & 3;          // 0..3 -> 32-row band
    const int warp_n = wid >> 2;         // 0..1 -> 32-col band
    const int row0 = blockIdx.x * 128;

    float acc[2][4][4];
    #pragma unroll
    for (int mt = 0; mt < 2; mt++)
        #pragma unroll
        for (int nt = 0; nt < 4; nt++)
            #pragma unroll
            for (int c = 0; c < 4; c++) acc[mt][nt][c] = 0.f;

    for (int ko = 0; ko < K; ko += 32) {
        // ---- stage x chunk [128 x 32] fp32 -> bf16 hi/lo ----
        #pragma unroll
        for (int i = 0; i < 16; i++) {
            int idx = tid + i * 256;       // 0..4095
            int r = idx >> 5;
            int c = idx & 31;
            int gr = row0 + r;
            int gk = ko + c;
            float v = (gr < nrows && gk < K) ? __ldg(&A[(long)gr * K + gk]) : 0.f;
            __nv_bfloat16 hb = __float2bfloat16(v);
            float hf = __bfloat162float(hb);
            __nv_bfloat16 lb = __float2bfloat16(v - hf);
            xs_hi[r * XS_STRIDE + c] = __bfloat16_as_ushort(hb);
            xs_lo[r * XS_STRIDE + c] = __bfloat16_as_ushort(lb);
        }
        // ---- stage W chunk [32 x 64] fp32 -> transposed bf16 hi/lo ----
        #pragma unroll
        for (int i = 0; i < 8; i++) {
            int idx = tid + i * 256;       // 0..2047
            int k = idx >> 6;
            int n = idx & 63;
            int gk = ko + k;
            float v = (gk < K) ? W[gk * 64 + n] : 0.f;
            __nv_bfloat16 hb = __float2bfloat16(v);
            float hf = __bfloat162float(hb);
            __nv_bfloat16 lb = __float2bfloat16(v - hf);
            wt_hi[n * XS_STRIDE + k] = __bfloat16_as_ushort(hb);
            wt_lo[n * XS_STRIDE + k] = __bfloat16_as_ushort(lb);
        }
        __syncthreads();

        #pragma unroll
        for (int ks = 0; ks < 2; ks++) {
            const int kk = ks * 16;
            unsigned ahi[2][4], alo[2][4];
            #pragma unroll
            for (int mt = 0; mt < 2; mt++) {
                int br = warp_m * 32 + mt * 16;
                const unsigned short* ph = &xs_hi[(br + g) * XS_STRIDE + kk + tg2];
                const unsigned short* pl = &xs_lo[(br + g) * XS_STRIDE + kk + tg2];
                ahi[mt][0] = *(const unsigned*)(ph);
                ahi[mt][1] = *(const unsigned*)(ph + 8 * XS_STRIDE);
                ahi[mt][2] = *(const unsigned*)(ph + 8);
                ahi[mt][3] = *(const unsigned*)(ph + 8 * XS_STRIDE + 8);
                alo[mt][0] = *(const unsigned*)(pl);
                alo[mt][1] = *(const unsigned*)(pl + 8 * XS_STRIDE);
                alo[mt][2] = *(const unsigned*)(pl + 8);
                alo[mt][3] = *(const unsigned*)(pl + 8 * XS_STRIDE + 8);
            }
            #pragma unroll
            for (int nt = 0; nt < 4; nt++) {
                int bn = warp_n * 32 + nt * 8 + g;
                const unsigned short* qh = &wt_hi[bn * XS_STRIDE + kk + tg2];
                const unsigned short* ql = &wt_lo[bn * XS_STRIDE + kk + tg2];
                unsigned bh0 = *(const unsigned*)(qh);
                unsigned bh1 = *(const unsigned*)(qh + 8);
                unsigned bl0 = *(const unsigned*)(ql);
                unsigned bl1 = *(const unsigned*)(ql + 8);
                #pragma unroll
                for (int mt = 0; mt < 2; mt++) {
                    MMA_BF16(acc[mt][nt], ahi[mt], bh0, bh1);
                    MMA_BF16(acc[mt][nt], ahi[mt], bl0, bl1);
                    MMA_BF16(acc[mt][nt], alo[mt], bh0, bh1);
                }
            }
        }
        __syncthreads();
    }

    // ---- epilogue: bias + relu, fp32 out ----
    #pragma unroll
    for (int mt = 0; mt < 2; mt++) {
        int r0 = row0 + warp_m * 32 + mt * 16 + g;
        int r1 = r0 + 8;
        #pragma unroll
        for (int nt = 0; nt < 4; nt++) {
            int col = warp_n * 32 + nt * 8 + tg2;
            float b0 = bias[col], b1 = bias[col + 1];
            if (r0 < nrows) {
                float v0 = fmaxf(acc[mt][nt][0] + b0, 0.f);
                float v1 = fmaxf(acc[mt][nt][1] + b1, 0.f);
                *(float2*)&C[(long)r0 * 64 + col] = make_float2(v0, v1);
            }
            if (r1 < nrows) {
                float v2 = fmaxf(acc[mt][nt][2] + b0, 0.f);
                float v3 = fmaxf(acc[mt][nt][3] + b1, 0.f);
                *(float2*)&C[(long)r1 * 64 + col] = make_float2(v2, v3);
            }
        }
    }
}

// ---------------- GEMM2 (fp32 FMA2, double-buffered) ----------------
template <bool RELU, bool WRITE_HALF>
__global__ __launch_bounds__(256)
void gemm128_kernel(const float* __restrict__ A, const float* __restrict__ W,
                    const float* __restrict__ bias, float* __restrict__ C,
                    __half* __restrict__ Yh, int nrows, int K) {
    __shared__ __align__(16) u64 xs[2][128 * KK];
    __shared__ __align__(16) u64 ws[2][KK * 32];

    const int tid  = threadIdx.x;
    const int w    = tid >> 5;
    const int lane = tid & 31;
    const int rh   = lane >> 4;
    const int cg   = lane & 15;
    const int rbase = w * 16 + rh * 8;
    const int row0  = blockIdx.x * 128;

    const int xr[4] = { (tid) >> 3, (tid + 256) >> 3, (tid + 512) >> 3, (tid + 768) >> 3 };
    const int xk = tid & 7;
    const int wkk = tid >> 5;
    const int wp  = tid & 31;

    u64 acc[8][2];
    #pragma unroll
    for (int r = 0; r < 8; r++) { acc[r][0] = 0ull; acc[r][1] = 0ull; }

    const int ktiles = (K + KK - 1) / KK;

    float xv[4];
    float wv0, wv1;

    {
        #pragma unroll
        for (int j = 0; j < 4; j++) {
            int gr = row0 + xr[j];
            xv[j] = (gr < nrows && xk < K) ? __ldg(&A[(long)gr * K + xk]) : 0.f;
        }
        wv0 = (wkk < K) ? W[wkk * 64 + 2 * wp]     : 0.f;
        wv1 = (wkk < K) ? W[wkk * 64 + 2 * wp + 1] : 0.f;
    }
    #pragma unroll
    for (int j = 0; j < 4; j++) xs[0][xr[j] * KK + xk] = pack2(xv[j], xv[j]);
    ws[0][wkk * 32 + wp] = pack2(wv0, wv1);
    __syncthreads();

    for (int t = 0; t < ktiles; t++) {
        const int buf = t & 1;
        if (t + 1 < ktiles) {
            const int ko = (t + 1) * KK;
            #pragma unroll
            for (int j = 0; j < 4; j++) {
                int gr = row0 + xr[j];
                int gk = ko + xk;
                xv[j] = (gr < nrows && gk < K) ? __ldg(&A[(long)gr * K + gk]) : 0.f;
            }
            int gk = ko + wkk;
            wv0 = (gk < K) ? W[gk * 64 + 2 * wp]     : 0.f;
            wv1 = (gk < K) ? W[gk * 64 + 2 * wp + 1] : 0.f;
        }

        u64 wr[KK][2];
        #pragma unroll
        for (int kk = 0; kk < KK; kk++) {
            ulonglong2 wv = *(const ulonglong2*)&ws[buf][kk * 32 + 2 * cg];
            wr[kk][0] = wv.x; wr[kk][1] = wv.y;
        }
        #pragma unroll
        for (int kk2 = 0; kk2 < KK / 2; kk2++) {
            #pragma unroll
            for (int r = 0; r < 8; r++) {
                ulonglong2 xq = *(const ulonglong2*)&xs[buf][(rbase + r) * KK + 2 * kk2];
                FMA2(acc[r][0], xq.x, wr[2 * kk2][0]);
                FMA2(acc[r][1], xq.x, wr[2 * kk2][1]);
                FMA2(acc[r][0], xq.y, wr[2 * kk2 + 1][0]);
                FMA2(acc[r][1], xq.y, wr[2 * kk2 + 1][1]);
            }
        }

        if (t + 1 < ktiles) {
            #pragma unroll
            for (int j = 0; j < 4; j++) xs[buf ^ 1][xr[j] * KK + xk] = pack2(xv[j], xv[j]);
            ws[buf ^ 1][wkk * 32 + wp] = pack2(wv0, wv1);
            __syncthreads();
        }
    }

    float4 b4 = *(const float4*)&bias[4 * cg];
    #pragma unroll
    for (int r = 0; r < 8; r++) {
        int row = row0 + rbase + r;
        if (row < nrows) {
            float c0, c1, c2, c3;
            unpack2(c0, c1, acc[r][0]);
            unpack2(c2, c3, acc[r][1]);
            c0 += b4.x; c1 += b4.y; c2 += b4.z; c3 += b4.w;
            if (RELU) {
                c0 = fmaxf(c0, 0.f); c1 = fmaxf(c1, 0.f);
                c2 = fmaxf(c2, 0.f); c3 = fmaxf(c3, 0.f);
            }
            *(float4*)&C[(long)row * 64 + 4 * cg] = make_float4(c0, c1, c2, c3);
            if (WRITE_HALF) {
                long yi = (long)row * 64 + 4 * cg;
                __half2 p0 = __floats2half2_rn(c0, c1);
                __half2 p1 = __floats2half2_rn(c2, c3);
                uint2 pv; pv.x = *(unsigned*)&p0; pv.y = *(unsigned*)&p1;
                *(uint2*)&Yh[yi] = pv;
            }
        }
    }
}

// ---------------- APPNP propagation (half-warp per edge, balanced tail) ----
#define PAIR_BODY(PJ) {                                                       \
    float wj = (float)((PJ) >> 17) * WQ_INV;                                  \
    uint2 v = *(const uint2*)(yin + ((long)((PJ) & 0x1FFFFu) << 6) + (hl << 2)); \
    float2 f0 = __half22float2(*(__half2*)&v.x);                              \
    float2 f1 = __half22float2(*(__half2*)&v.y);                              \
    a0 = fmaf(wj, f0.x, a0); a1 = fmaf(wj, f0.y, a1);                         \
    a2 = fmaf(wj, f1.x, a2); a3 = fmaf(wj, f1.y, a3); }

template <bool FINAL>
__global__ __launch_bounds__(256)
void prop_kernel(const __half* __restrict__ yin,
                 const uint2* __restrict__ hh, const float4* __restrict__ h4,
                 uint2* __restrict__ yout, float4* __restrict__ fout,
                 float c1, float c2) {
    int gtid = blockIdx.x * blockDim.x + threadIdx.x;
    int node = gtid >> 5;
    int lane = threadIdx.x & 31;
    if (node >= N_NODES) return;
    const int hl = lane & 15;

    int beg = g_off[node];
    int end = g_off[node + 1];

    float a0 = 0.f, a1 = 0.f, a2 = 0.f, a3 = 0.f;
    int e = beg;
    for (; e + 32 <= end; e += 32) {
        unsigned pe = __ldg(&g_epk[e + lane]);
        #pragma unroll
        for (int j = 0; j < 16; j++) {
            unsigned pj = __shfl_sync(0xffffffffu, pe, j, 16);
            PAIR_BODY(pj)
        }
    }
    if (e < end) {
        int idx = e + lane;
        unsigned pe = (idx < end) ? __ldg(&g_epk[idx]) : 0u;
        int cnt  = end - e;                 // 1..31
        int jcnt = (cnt + 1) >> 1;
        int hoff = (lane & 16) ? jcnt : 0;
        for (int j = 0; j < jcnt; j++) {
            unsigned pj = __shfl_sync(0xffffffffu, pe, j + hoff, 32);
            PAIR_BODY(pj)
        }
    }
    a0 += __shfl_xor_sync(0xffffffffu, a0, 16);
    a1 += __shfl_xor_sync(0xffffffffu, a1, 16);
    a2 += __shfl_xor_sync(0xffffffffu, a2, 16);
    a3 += __shfl_xor_sync(0xffffffffu, a3, 16);

    if (lane < 16) {
        long oi = (long)node * 16 + hl;
        if (FINAL) {
            float4 hv = h4[oi];
            fout[oi] = make_float4(fmaf(c1, a0, c2 * hv.x),
                                   fmaf(c1, a1, c2 * hv.y),
                                   fmaf(c1, a2, c2 * hv.z),
                                   fmaf(c1, a3, c2 * hv.w));
        } else {
            uint2 hv2 = hh[oi];
            float2 f0 = __half22float2(*(__half2*)&hv2.x);
            float2 f1 = __half22float2(*(__half2*)&hv2.y);
            __half2 p0 = __floats2half2_rn(fmaf(c1, a0, c2 * f0.x),
                                           fmaf(c1, a1, c2 * f0.y));
            __half2 p1 = __floats2half2_rn(fmaf(c1, a2, c2 * f1.x),
                                           fmaf(c1, a3, c2 * f1.y));
            uint2 pv; pv.x = *(unsigned*)&p0; pv.y = *(unsigned*)&p1;
            yout[oi] = pv;
        }
    }
}

// ---------------- launch ----------------
extern "C" void kernel_launch(void* const* d_in, const int* in_sizes, int n_in,
                              void* d_out, int out_size) {
    const float* x    = (const float*)d_in[0];
    const int*   esrc = (const int*)d_in[1];
    const int*   edst = (const int*)d_in[2];
    const float* ew   = (const float*)d_in[3];
    const float* W1   = (const float*)d_in[4];
    const float* b1   = (const float*)d_in[5];
    const float* W2   = (const float*)d_in[6];
    const float* b2   = (const float*)d_in[7];
    float* out = (float*)d_out;

    static cudaStream_t s_side = nullptr;
    static cudaEvent_t  s_evFork = nullptr, s_evJoin = nullptr;
    if (!s_side) {
        cudaStreamCreateWithFlags(&s_side, cudaStreamNonBlocking);
        cudaEventCreateWithFlags(&s_evFork, cudaEventDisableTiming);
        cudaEventCreateWithFlags(&s_evJoin, cudaEventDisableTiming);
    }

    float  *h1_p, *h_p;
    __half *hh_p, *ya_p, *yb_p;
    cudaGetSymbolAddress((void**)&h1_p, g_h1);
    cudaGetSymbolAddress((void**)&h_p,  g_h);
    cudaGetSymbolAddress((void**)&hh_p, g_hh);
    cudaGetSymbolAddress((void**)&ya_p, g_ya);
    cudaGetSymbolAddress((void**)&yb_p, g_yb);

    // --- fork: CSR build on side stream, concurrent with MLP GEMMs ---
    cudaEventRecord(s_evFork, 0);
    cudaStreamWaitEvent(s_side, s_evFork, 0);
    hist_kernel<<<(N_EDGES / 4 + 255) / 256, 256, 0, s_side>>>(edst);
    scan_local_kernel<<<NSCAN_BLOCKS, 1024, 0, s_side>>>();
    scan_add_kernel<<<NSCAN_BLOCKS, 1024, 0, s_side>>>();
    scatter_kernel<<<(N_EDGES + 255) / 256, 256, 0, s_side>>>(esrc, edst, ew);
    cudaEventRecord(s_evJoin, s_side);

    // --- MLP encoder: tensor-core GEMM1, FMA2 GEMM2 (emits fp16 h too) ---
    int gblocks = (N_NODES + 127) / 128;
    gemm1_tc_kernel<<<gblocks, 256>>>(x, W1, b1, h1_p, N_NODES, IN_F);
    gemm128_kernel<false, true><<<gblocks, 256>>>(h1_p, W2, b2, h_p, hh_p,
                                                  N_NODES, HID);

    // --- join, then K propagation steps ---
    cudaStreamWaitEvent(0, s_evJoin, 0);

    int pblocks = (N_NODES * 32 + 255) / 256;
    const __half* yin = hh_p;                 // y_0 = fp16(h)
    __half* ybufs[2] = { ya_p, yb_p };
    for (int k = 0; k < K_ITERS; k++) {
        if (k < K_ITERS - 1) {
            float c1 = (float)(0.9 * SCALE_S);
            float c2 = (float)(0.1 * pow(SCALE_S, (double)(k + 1)));
            __half* yo = ybufs[k & 1];
            prop_kernel<false><<<pblocks, 256>>>(yin, (const uint2*)hh_p, nullptr,
                                                 (uint2*)yo, nullptr, c1, c2);
            yin = yo;
        } else {
            float c1 = (float)(0.9 * pow(1.0 / SCALE_S, (double)(K_ITERS - 1)));
            float c2 = 0.1f;
            prop_kernel<true><<<pblocks, 256>>>(yin, nullptr, (const float4*)h_p,
                                                nullptr, (float4*)out, c1, c2);
        }
    }
}

// round 14
// speedup vs baseline: 1.2440x; 1.1306x over previous
#include <cuda_runtime.h>
#include <cuda_bf16.h>
#include <cuda_fp16.h>
#include <math.h>

// ---------------- problem constants ----------------
#define N_NODES 100000
#define N_EDGES 3200000
#define IN_F    500
#define HID     64
#define OUT_F   64
#define ALPHA   0.1f
#define K_ITERS 10

#define NSCAN_BLOCKS ((N_NODES + 1023) / 1024)   // 98
#define SCALE_S 0.0625                            // 1/16 per-iteration z scaling
#define WQ_SCALE 32767.0f
#define WQ_INV   (1.0f / 32767.0f)

typedef unsigned long long u64;

// ---------------- static device scratch ----------------
__device__ float    g_h [N_NODES * OUT_F];        // fp32 h (final iter)
__device__ __half   g_hh[N_NODES * OUT_F];        // fp16 h (= y_0, alpha term)
__device__ __half   g_ya[N_NODES * OUT_F];        // fp16 iterate ping
__device__ __half   g_yb[N_NODES * OUT_F];        // fp16 iterate pong
__device__ int      g_deg[N_NODES];               // ALWAYS zero at launch entry
__device__ int      g_off[N_NODES + 1];
__device__ int      g_pos[N_NODES];
__device__ unsigned g_epk[N_EDGES];               // packed edge: w15 | src17
__device__ int      g_bsum[NSCAN_BLOCKS];

// ---------------- CSR construction (4 kernels) ----------------
__global__ void hist_kernel(const int* __restrict__ dst) {
    int i = blockIdx.x * blockDim.x + threadIdx.x;
    if (i * 4 + 3 < N_EDGES) {
        int4 d = ((const int4*)dst)[i];
        atomicAdd(&g_deg[d.x], 1);
        atomicAdd(&g_deg[d.y], 1);
        atomicAdd(&g_deg[d.z], 1);
        atomicAdd(&g_deg[d.w], 1);
    } else {
        for (int e = i * 4; e < N_EDGES; e++) atomicAdd(&g_deg[dst[e]], 1);
    }
}

__global__ void scan_local_kernel() {
    __shared__ int s[1024];
    int tid = threadIdx.x;
    int i = blockIdx.x * 1024 + tid;
    int v = (i < N_NODES) ? g_deg[i] : 0;
    s[tid] = v;
    __syncthreads();
    #pragma unroll
    for (int d = 1; d < 1024; d <<= 1) {
        int t = (tid >= d) ? s[tid - d] : 0;
        __syncthreads();
        s[tid] += t;
        __syncthreads();
    }
    if (i < N_NODES) {
        g_off[i] = s[tid] - v;     // exclusive local
        g_deg[i] = 0;              // restore zero invariant for next launch
    }
    if (tid == 1023) g_bsum[blockIdx.x] = s[1023];
}

__global__ void scan_add_kernel() {
    __shared__ int red[32];
    int tid  = threadIdx.x;
    int lane = tid & 31;
    int wid  = tid >> 5;
    int pre = 0;
    for (int t = tid; t < blockIdx.x; t += 1024) pre += g_bsum[t];
    #pragma unroll
    for (int d = 16; d; d >>= 1) pre += __shfl_down_sync(0xffffffffu, pre, d);
    if (lane == 0) red[wid] = pre;
    __syncthreads();
    if (wid == 0) {
        int v = red[lane];
        #pragma unroll
        for (int d = 16; d; d >>= 1) v += __shfl_down_sync(0xffffffffu, v, d);
        if (lane == 0) red[0] = v;
    }
    __syncthreads();
    int base = red[0];

    int i = blockIdx.x * 1024 + tid;
    if (i < N_NODES) {
        int o = g_off[i] + base;
        g_off[i] = o;
        g_pos[i] = o;
    }
    if (blockIdx.x == 0 && tid == 0) g_off[N_NODES] = N_EDGES;
}

__global__ void scatter_kernel(const int* __restrict__ src,
                               const int* __restrict__ dst,
                               const float* __restrict__ w) {
    int e = blockIdx.x * blockDim.x + threadIdx.x;
    if (e < N_EDGES) {
        int d = dst[e];
        int p = atomicAdd(&g_pos[d], 1);
        unsigned q = (unsigned)__float2int_rn(w[e] * WQ_SCALE);
        g_epk[p] = (q << 17) | (unsigned)src[e];
    }
}

// ---------------- fused MLP on tensor cores ----------------
// h = relu(x@W1+b1)@W2 + b2, bf16 hi/lo split (3 MMA passes), fp32 acc.
// Block = 128 rows; 8 warps in 4(m) x 2(n); warp tile 32x32.
// Stage 1: K=500 chunked by 32 (stride-40 smem). Stage 2: h1 tile (regs) ->
// bias+relu -> bf16 hi/lo into stride-72 smem (aliases dead stage-1 buffers),
// W2^T staged likewise, 4 k-steps of MMA, epilogue writes fp32 + fp16 h.
#define S1_STRIDE 40
#define S2_STRIDE 72
// dynamic smem partition (ushort units)
#define OFF_XA    0                        // stage1 xs_hi | stage2 h1_hi
#define OFF_XB    9216                     // stage1 xs_lo(@5120 in A).. see code
#define OFF_WREG  18432                    // stage1 wt hi/lo | stage2 w2t hi/lo
#define SMEM_MLP_USHORT (18432 + 9216)     // 27648 ushorts
#define SMEM_MLP_BYTES  (SMEM_MLP_USHORT * 2)   // 55296 B

#define MMA_BF16(d, a, b0_, b1_)                                              \
    asm volatile("mma.sync.aligned.m16n8k16.row.col.f32.bf16.bf16.f32 "       \
                 "{%0,%1,%2,%3}, {%4,%5,%6,%7}, {%8,%9}, {%0,%1,%2,%3};"      \
                 : "+f"(d[0]), "+f"(d[1]), "+f"(d[2]), "+f"(d[3])             \
                 : "r"(a[0]), "r"(a[1]), "r"(a[2]), "r"(a[3]),                \
                   "r"(b0_), "r"(b1_))

__device__ __forceinline__ void bf16_split(float v, unsigned short& h,
                                           unsigned short& l) {
    __nv_bfloat16 hb = __float2bfloat16(v);
    float hf = __bfloat162float(hb);
    __nv_bfloat16 lb = __float2bfloat16(v - hf);
    h = __bfloat16_as_ushort(hb);
    l = __bfloat16_as_ushort(lb);
}

__global__ __launch_bounds__(256)
void mlp_tc_kernel(const float* __restrict__ A,
                   const float* __restrict__ W1, const float* __restrict__ b1,
                   const float* __restrict__ W2, const float* __restrict__ b2,
                   float* __restrict__ H, __half* __restrict__ Hh, int nrows) {
    extern __shared__ unsigned short sm[];
    // stage-1 views
    unsigned short* xs_hi = sm;                         // 128*40
    unsigned short* xs_lo = sm + 128 * S1_STRIDE;       // 128*40 (ends 10240)
    unsigned short* wt_hi = sm + OFF_WREG;              // 64*40
    unsigned short* wt_lo = sm + OFF_WREG + 64 * S1_STRIDE;
    // stage-2 views (alias)
    unsigned short* h1_hi = sm;                         // 128*72
    unsigned short* h1_lo = sm + 128 * S2_STRIDE;       // 128*72 (ends 18432)
    unsigned short* w2_hi = sm + OFF_WREG;              // 64*72
    unsigned short* w2_lo = sm + OFF_WREG + 64 * S2_STRIDE;

    const int tid  = threadIdx.x;
    const int wid  = tid >> 5;
    const int lane = tid & 31;
    const int g    = lane >> 2;
    const int tg2  = (lane & 3) * 2;
    const int warp_m = wid & 3;
    const int warp_n = wid >> 2;
    const int row0 = blockIdx.x * 128;

    float acc[2][4][4];
    #pragma unroll
    for (int mt = 0; mt < 2; mt++)
        #pragma unroll
        for (int nt = 0; nt < 4; nt++)
            #pragma unroll
            for (int c = 0; c < 4; c++) acc[mt][nt][c] = 0.f;

    // ================= stage 1: h1 = x @ W1 =================
    for (int ko = 0; ko < IN_F; ko += 32) {
        #pragma unroll
        for (int i = 0; i < 16; i++) {
            int idx = tid + i * 256;
            int r = idx >> 5;
            int c = idx & 31;
            int gr = row0 + r;
            int gk = ko + c;
            float v = (gr < nrows && gk < IN_F) ? __ldg(&A[(long)gr * IN_F + gk]) : 0.f;
            unsigned short hv, lv;
            bf16_split(v, hv, lv);
            xs_hi[r * S1_STRIDE + c] = hv;
            xs_lo[r * S1_STRIDE + c] = lv;
        }
        #pragma unroll
        for (int i = 0; i < 8; i++) {
            int idx = tid + i * 256;
            int k = idx >> 6;
            int n = idx & 63;
            int gk = ko + k;
            float v = (gk < IN_F) ? W1[gk * 64 + n] : 0.f;
            unsigned short hv, lv;
            bf16_split(v, hv, lv);
            wt_hi[n * S1_STRIDE + k] = hv;
            wt_lo[n * S1_STRIDE + k] = lv;
        }
        __syncthreads();

        #pragma unroll
        for (int ks = 0; ks < 2; ks++) {
            const int kk = ks * 16;
            unsigned ahi[2][4], alo[2][4];
            #pragma unroll
            for (int mt = 0; mt < 2; mt++) {
                int br = warp_m * 32 + mt * 16;
                const unsigned short* ph = &xs_hi[(br + g) * S1_STRIDE + kk + tg2];
                const unsigned short* pl = &xs_lo[(br + g) * S1_STRIDE + kk + tg2];
                ahi[mt][0] = *(const unsigned*)(ph);
                ahi[mt][1] = *(const unsigned*)(ph + 8 * S1_STRIDE);
                ahi[mt][2] = *(const unsigned*)(ph + 8);
                ahi[mt][3] = *(const unsigned*)(ph + 8 * S1_STRIDE + 8);
                alo[mt][0] = *(const unsigned*)(pl);
                alo[mt][1] = *(const unsigned*)(pl + 8 * S1_STRIDE);
                alo[mt][2] = *(const unsigned*)(pl + 8);
                alo[mt][3] = *(const unsigned*)(pl + 8 * S1_STRIDE + 8);
            }
            #pragma unroll
            for (int nt = 0; nt < 4; nt++) {
                int bn = warp_n * 32 + nt * 8 + g;
                const unsigned short* qh = &wt_hi[bn * S1_STRIDE + kk + tg2];
                const unsigned short* ql = &wt_lo[bn * S1_STRIDE + kk + tg2];
                unsigned bh0 = *(const unsigned*)(qh);
                unsigned bh1 = *(const unsigned*)(qh + 8);
                unsigned bl0 = *(const unsigned*)(ql);
                unsigned bl1 = *(const unsigned*)(ql + 8);
                #pragma unroll
                for (int mt = 0; mt < 2; mt++) {
                    MMA_BF16(acc[mt][nt], ahi[mt], bh0, bh1);
                    MMA_BF16(acc[mt][nt], ahi[mt], bl0, bl1);
                    MMA_BF16(acc[mt][nt], alo[mt], bh0, bh1);
                }
            }
        }
        __syncthreads();
    }

    // ============ inter-stage: bias1 + relu, h1 -> smem (bf16 hi/lo) ========
    #pragma unroll
    for (int mt = 0; mt < 2; mt++) {
        int r0 = warp_m * 32 + mt * 16 + g;       // local rows
        int r1 = r0 + 8;
        #pragma unroll
        for (int nt = 0; nt < 4; nt++) {
            int col = warp_n * 32 + nt * 8 + tg2;
            float bb0 = b1[col], bb1 = b1[col + 1];
            float v0 = fmaxf(acc[mt][nt][0] + bb0, 0.f);
            float v1 = fmaxf(acc[mt][nt][1] + bb1, 0.f);
            float v2 = fmaxf(acc[mt][nt][2] + bb0, 0.f);
            float v3 = fmaxf(acc[mt][nt][3] + bb1, 0.f);
            unsigned short h0, l0, h1v, l1, h2, l2, h3, l3;
            bf16_split(v0, h0, l0); bf16_split(v1, h1v, l1);
            bf16_split(v2, h2, l2); bf16_split(v3, h3, l3);
            // packed 32-bit stores (col even, stride even -> aligned)
            *(unsigned*)&h1_hi[r0 * S2_STRIDE + col] = (unsigned)h0 | ((unsigned)h1v << 16);
            *(unsigned*)&h1_lo[r0 * S2_STRIDE + col] = (unsigned)l0 | ((unsigned)l1 << 16);
            *(unsigned*)&h1_hi[r1 * S2_STRIDE + col] = (unsigned)h2 | ((unsigned)h3 << 16);
            *(unsigned*)&h1_lo[r1 * S2_STRIDE + col] = (unsigned)l2 | ((unsigned)l3 << 16);
            // reset accumulators for stage 2
            acc[mt][nt][0] = 0.f; acc[mt][nt][1] = 0.f;
            acc[mt][nt][2] = 0.f; acc[mt][nt][3] = 0.f;
        }
    }
    // stage W2^T (64x64) hi/lo
    #pragma unroll
    for (int i = 0; i < 16; i++) {
        int idx = tid + i * 256;                  // 0..4095
        int k = idx >> 6;
        int n = idx & 63;
        float v = W2[k * 64 + n];
        unsigned short hv, lv;
        bf16_split(v, hv, lv);
        w2_hi[n * S2_STRIDE + k] = hv;
        w2_lo[n * S2_STRIDE + k] = lv;
    }
    __syncthreads();

    // ================= stage 2: h = h1 @ W2 (K=64) =================
    #pragma unroll
    for (int ks = 0; ks < 4; ks++) {
        const int kk = ks * 16;
        unsigned ahi[2][4], alo[2][4];
        #pragma unroll
        for (int mt = 0; mt < 2; mt++) {
            int br = warp_m * 32 + mt * 16;
            const unsigned short* ph = &h1_hi[(br + g) * S2_STRIDE + kk + tg2];
            const unsigned short* pl = &h1_lo[(br + g) * S2_STRIDE + kk + tg2];
            ahi[mt][0] = *(const unsigned*)(ph);
            ahi[mt][1] = *(const unsigned*)(ph + 8 * S2_STRIDE);
            ahi[mt][2] = *(const unsigned*)(ph + 8);
            ahi[mt][3] = *(const unsigned*)(ph + 8 * S2_STRIDE + 8);
            alo[mt][0] = *(const unsigned*)(pl);
            alo[mt][1] = *(const unsigned*)(pl + 8 * S2_STRIDE);
            alo[mt][2] = *(const unsigned*)(pl + 8);
            alo[mt][3] = *(const unsigned*)(pl + 8 * S2_STRIDE + 8);
        }
        #pragma unroll
        for (int nt = 0; nt < 4; nt++) {
            int bn = warp_n * 32 + nt * 8 + g;
            const unsigned short* qh = &w2_hi[bn * S2_STRIDE + kk + tg2];
            const unsigned short* ql = &w2_lo[bn * S2_STRIDE + kk + tg2];
            unsigned bh0 = *(const unsigned*)(qh);
            unsigned bh1 = *(const unsigned*)(qh + 8);
            unsigned bl0 = *(const unsigned*)(ql);
            unsigned bl1 = *(const unsigned*)(ql + 8);
            #pragma unroll
            for (int mt = 0; mt < 2; mt++) {
                MMA_BF16(acc[mt][nt], ahi[mt], bh0, bh1);
                MMA_BF16(acc[mt][nt], ahi[mt], bl0, bl1);
                MMA_BF16(acc[mt][nt], alo[mt], bh0, bh1);
            }
        }
    }

    // ============ epilogue: bias2, write fp32 h + fp16 h ============
    #pragma unroll
    for (int mt = 0; mt < 2; mt++) {
        int r0 = row0 + warp_m * 32 + mt * 16 + g;
        int r1 = r0 + 8;
        #pragma unroll
        for (int nt = 0; nt < 4; nt++) {
            int col = warp_n * 32 + nt * 8 + tg2;
            float bb0 = b2[col], bb1 = b2[col + 1];
            if (r0 < nrows) {
                float v0 = acc[mt][nt][0] + bb0;
                float v1 = acc[mt][nt][1] + bb1;
                *(float2*)&H[(long)r0 * 64 + col] = make_float2(v0, v1);
                __half2 p = __floats2half2_rn(v0, v1);
                *(unsigned*)&Hh[(long)r0 * 64 + col] = *(unsigned*)&p;
            }
            if (r1 < nrows) {
                float v2 = acc[mt][nt][2] + bb0;
                float v3 = acc[mt][nt][3] + bb1;
                *(float2*)&H[(long)r1 * 64 + col] = make_float2(v2, v3);
                __half2 p = __floats2half2_rn(v2, v3);
                *(unsigned*)&Hh[(long)r1 * 64 + col] = *(unsigned*)&p;
            }
        }
    }
}

// ---------------- APPNP propagation (half-warp per edge, balanced tail) ----
#define PAIR_BODY(PJ) {                                                       \
    float wj = (float)((PJ) >> 17) * WQ_INV;                                  \
    uint2 v = *(const uint2*)(yin + ((long)((PJ) & 0x1FFFFu) << 6) + (hl << 2)); \
    float2 f0 = __half22float2(*(__half2*)&v.x);                              \
    float2 f1 = __half22float2(*(__half2*)&v.y);                              \
    a0 = fmaf(wj, f0.x, a0); a1 = fmaf(wj, f0.y, a1);                         \
    a2 = fmaf(wj, f1.x, a2); a3 = fmaf(wj, f1.y, a3); }

template <bool FINAL>
__global__ __launch_bounds__(256)
void prop_kernel(const __half* __restrict__ yin,
                 const uint2* __restrict__ hh, const float4* __restrict__ h4,
                 uint2* __restrict__ yout, float4* __restrict__ fout,
                 float c1, float c2) {
    int gtid = blockIdx.x * blockDim.x + threadIdx.x;
    int node = gtid >> 5;
    int lane = threadIdx.x & 31;
    if (node >= N_NODES) return;
    const int hl = lane & 15;

    int beg = g_off[node];
    int end = g_off[node + 1];

    float a0 = 0.f, a1 = 0.f, a2 = 0.f, a3 = 0.f;
    int e = beg;
    for (; e + 32 <= end; e += 32) {
        unsigned pe = __ldg(&g_epk[e + lane]);
        #pragma unroll
        for (int j = 0; j < 16; j++) {
            unsigned pj = __shfl_sync(0xffffffffu, pe, j, 16);
            PAIR_BODY(pj)
        }
    }
    if (e < end) {
        int idx = e + lane;
        unsigned pe = (idx < end) ? __ldg(&g_epk[idx]) : 0u;
        int cnt  = end - e;                 // 1..31
        int jcnt = (cnt + 1) >> 1;
        int hoff = (lane & 16) ? jcnt : 0;
        for (int j = 0; j < jcnt; j++) {
            unsigned pj = __shfl_sync(0xffffffffu, pe, j + hoff, 32);
            PAIR_BODY(pj)
        }
    }
    a0 += __shfl_xor_sync(0xffffffffu, a0, 16);
    a1 += __shfl_xor_sync(0xffffffffu, a1, 16);
    a2 += __shfl_xor_sync(0xffffffffu, a2, 16);
    a3 += __shfl_xor_sync(0xffffffffu, a3, 16);

    if (lane < 16) {
        long oi = (long)node * 16 + hl;
        if (FINAL) {
            float4 hv = h4[oi];
            fout[oi] = make_float4(fmaf(c1, a0, c2 * hv.x),
                                   fmaf(c1, a1, c2 * hv.y),
                                   fmaf(c1, a2, c2 * hv.z),
                                   fmaf(c1, a3, c2 * hv.w));
        } else {
            uint2 hv2 = hh[oi];
            float2 f0 = __half22float2(*(__half2*)&hv2.x);
            float2 f1 = __half22float2(*(__half2*)&hv2.y);
            __half2 p0 = __floats2half2_rn(fmaf(c1, a0, c2 * f0.x),
                                           fmaf(c1, a1, c2 * f0.y));
            __half2 p1 = __floats2half2_rn(fmaf(c1, a2, c2 * f1.x),
                                           fmaf(c1, a3, c2 * f1.y));
            uint2 pv; pv.x = *(unsigned*)&p0; pv.y = *(unsigned*)&p1;
            yout[oi] = pv;
        }
    }
}

// ---------------- launch ----------------
extern "C" void kernel_launch(void* const* d_in, const int* in_sizes, int n_in,
                              void* d_out, int out_size) {
    const float* x    = (const float*)d_in[0];
    const int*   esrc = (const int*)d_in[1];
    const int*   edst = (const int*)d_in[2];
    const float* ew   = (const float*)d_in[3];
    const float* W1   = (const float*)d_in[4];
    const float* b1   = (const float*)d_in[5];
    const float* W2   = (const float*)d_in[6];
    const float* b2   = (const float*)d_in[7];
    float* out = (float*)d_out;

    static cudaStream_t s_side = nullptr;
    static cudaEvent_t  s_evFork = nullptr, s_evJoin = nullptr;
    if (!s_side) {
        cudaStreamCreateWithFlags(&s_side, cudaStreamNonBlocking);
        cudaEventCreateWithFlags(&s_evFork, cudaEventDisableTiming);
        cudaEventCreateWithFlags(&s_evJoin, cudaEventDisableTiming);
        cudaFuncSetAttribute(mlp_tc_kernel,
                             cudaFuncAttributeMaxDynamicSharedMemorySize,
                             SMEM_MLP_BYTES);
    }

    float  *h_p;
    __half *hh_p, *ya_p, *yb_p;
    cudaGetSymbolAddress((void**)&h_p,  g_h);
    cudaGetSymbolAddress((void**)&hh_p, g_hh);
    cudaGetSymbolAddress((void**)&ya_p, g_ya);
    cudaGetSymbolAddress((void**)&yb_p, g_yb);

    // --- fork: CSR build on side stream, concurrent with fused MLP ---
    cudaEventRecord(s_evFork, 0);
    cudaStreamWaitEvent(s_side, s_evFork, 0);
    hist_kernel<<<(N_EDGES / 4 + 255) / 256, 256, 0, s_side>>>(edst);
    scan_local_kernel<<<NSCAN_BLOCKS, 1024, 0, s_side>>>();
    scan_add_kernel<<<NSCAN_BLOCKS, 1024, 0, s_side>>>();
    scatter_kernel<<<(N_EDGES + 255) / 256, 256, 0, s_side>>>(esrc, edst, ew);
    cudaEventRecord(s_evJoin, s_side);

    // --- fused MLP on main stream (writes fp32 h + fp16 h) ---
    int gblocks = (N_NODES + 127) / 128;
    mlp_tc_kernel<<<gblocks, 256, SMEM_MLP_BYTES>>>(x, W1, b1, W2, b2,
                                                    h_p, hh_p, N_NODES);

    // --- join, then K propagation steps ---
    cudaStreamWaitEvent(0, s_evJoin, 0);

    int pblocks = (N_NODES * 32 + 255) / 256;
    const __half* yin = hh_p;                 // y_0 = fp16(h)
    __half* ybufs[2] = { ya_p, yb_p };
    for (int k = 0; k < K_ITERS; k++) {
        if (k < K_ITERS - 1) {
            float c1 = (float)(0.9 * SCALE_S);
            float c2 = (float)(0.1 * pow(SCALE_S, (double)(k + 1)));
            __half* yo = ybufs[k & 1];
            prop_kernel<false><<<pblocks, 256>>>(yin, (const uint2*)hh_p, nullptr,
                                                 (uint2*)yo, nullptr, c1, c2);
            yin = yo;
        } else {
            float c1 = (float)(0.9 * pow(1.0 / SCALE_S, (double)(K_ITERS - 1)));
            float c2 = 0.1f;
            prop_kernel<true><<<pblocks, 256>>>(yin, nullptr, (const float4*)h_p,
                                                nullptr, (float4*)out, c1, c2);
        }
    }
}